// round 10
// baseline (speedup 1.0000x reference)
#include <cuda_runtime.h>
#include <cuda_fp16.h>
#include <cstdint>
#include <cstddef>

#define TLEN  512
#define BATCH 128
#define EDIM  128
#define HDIM  128
#define GDIM  512   // 4*H
#define VOCAB 100000

// Scratch (device globals — no allocation).
// xp layout: [dir][t][slice(16)][g(512)][8b]  fp16
static __device__ __half g_xp[(size_t)2 * TLEN * 16 * GDIM * 8];
static __device__ __align__(16) __half g_table_h[(size_t)VOCAB * EDIM];
static __device__ __align__(16) __half g_wih_h[2 * GDIM * EDIM];
static __device__ float g_pool[2 * BATCH * HDIM];

// ---------- helpers ----------
#define H_HALF2 0x38003800u   // {0.5,0.5} fp16
__device__ __forceinline__ unsigned hmul2(unsigned a, unsigned b) {
    unsigned d; asm("mul.rn.f16x2 %0,%1,%2;" : "=r"(d) : "r"(a), "r"(b)); return d;
}
__device__ __forceinline__ unsigned hfma2(unsigned a, unsigned b, unsigned c) {
    unsigned d; asm("fma.rn.f16x2 %0,%1,%2,%3;" : "=r"(d) : "r"(a), "r"(b), "r"(c)); return d;
}
__device__ __forceinline__ unsigned htanh2(unsigned a) {
    unsigned d; asm("tanh.approx.f16x2 %0,%1;" : "=r"(d) : "r"(a)); return d;
}
__device__ __forceinline__ unsigned hsig2(unsigned x) {   // 0.5*tanh(0.5x)+0.5
    return hfma2(htanh2(hmul2(x, H_HALF2)), H_HALF2, H_HALF2);
}
__device__ __forceinline__ unsigned hmax2u(unsigned a, unsigned b) {
    __half2 r = __hmax2(*(__half2*)&a, *(__half2*)&b);
    return *(unsigned*)&r;
}
__device__ __forceinline__ float2 h22f2(unsigned v) {
    return __half22float2(*(__half2*)&v);
}
__device__ __forceinline__ unsigned dup_h2(float v) {
    __half2 h = __half2half2(__float2half_rn(v));
    return *(unsigned*)&h;
}
__device__ __forceinline__ unsigned sptr(const void* p) {
    return (unsigned)__cvta_generic_to_shared(p);
}
__device__ __forceinline__ void cpa16(void* s, const void* g) {
    asm volatile("cp.async.cg.shared.global [%0], [%1], 16;" :: "r"(sptr(s)), "l"(g));
}
__device__ __forceinline__ void mmaf16(unsigned& d0, unsigned& d1,
                                       unsigned a0, unsigned a1, unsigned a2, unsigned a3,
                                       unsigned b0, unsigned b1) {
    asm("mma.sync.aligned.m16n8k16.row.col.f16.f16.f16.f16 "
        "{%0,%1},{%2,%3,%4,%5},{%6,%7},{%0,%1};"
        : "+r"(d0), "+r"(d1)
        : "r"(a0), "r"(a1), "r"(a2), "r"(a3), "r"(b0), "r"(b1));
}
__device__ __forceinline__ void ldsm4(unsigned& r0, unsigned& r1, unsigned& r2, unsigned& r3,
                                      unsigned addr) {
    asm volatile("ldmatrix.sync.aligned.m8n8.x4.shared.b16 {%0,%1,%2,%3}, [%4];"
                 : "=r"(r0), "=r"(r1), "=r"(r2), "=r"(r3) : "r"(addr));
}
__device__ __forceinline__ void ldsm4t(unsigned& r0, unsigned& r1, unsigned& r2, unsigned& r3,
                                       unsigned addr) {
    asm volatile("ldmatrix.sync.aligned.m8n8.x4.trans.shared.b16 {%0,%1,%2,%3}, [%4];"
                 : "=r"(r0), "=r"(r1), "=r"(r2), "=r"(r3) : "r"(addr));
}

// =====================================================================
// Kernel 0a/0b: one-time fp32 -> fp16 conversions (per launch)
// =====================================================================
__global__ void __launch_bounds__(256) conv_table_kernel(const float* __restrict__ t) {
    const size_t i = ((size_t)blockIdx.x * 256 + threadIdx.x) * 4;
    const float4 v = *(const float4*)(t + i);
    const __half2 a = __floats2half2_rn(v.x, v.y);
    const __half2 b = __floats2half2_rn(v.z, v.w);
    *(uint2*)&g_table_h[i] = make_uint2(*(const unsigned*)&a, *(const unsigned*)&b);
}
__global__ void __launch_bounds__(256) conv_wih_kernel(const float* __restrict__ wf,
                                                       const float* __restrict__ wb) {
    const int i = (blockIdx.x * 256 + threadIdx.x) * 4;
    {
        const float4 v = *(const float4*)(wf + i);
        const __half2 a = __floats2half2_rn(v.x, v.y);
        const __half2 b = __floats2half2_rn(v.z, v.w);
        *(uint2*)&g_wih_h[i] = make_uint2(*(const unsigned*)&a, *(const unsigned*)&b);
    }
    {
        const float4 v = *(const float4*)(wb + i);
        const __half2 a = __floats2half2_rn(v.x, v.y);
        const __half2 b = __floats2half2_rn(v.z, v.w);
        *(uint2*)&g_wih_h[GDIM * EDIM + i] = make_uint2(*(const unsigned*)&a, *(const unsigned*)&b);
    }
}

// =====================================================================
// Kernel 1: input projection, fp16 mma (f16 accum) + cp.async + ldmatrix.
// (unchanged from R8/R9 — ~70us)
// =====================================================================
#define PJ_STRIDE 136
#define PJ_SMEM (2 * 128 * PJ_STRIDE * 2)   // 69632 B

__global__ void __launch_bounds__(256, 2) proj_kernel(
    const int* __restrict__ x,
    const float* __restrict__ bih_f, const float* __restrict__ bhh_f,
    const float* __restrict__ bih_b, const float* __restrict__ bhh_b)
{
    extern __shared__ char dynsm[];
    __half* Wsm = (__half*)dynsm;             // [128][136]
    __half* Esm = Wsm + 128 * PJ_STRIDE;      // [128][136]
    __shared__ float bias_s[128];

    const int tid  = threadIdx.x, lane = tid & 31, w = tid >> 5;
    const int gtile = blockIdx.x;
    const int dir   = blockIdx.y >> 9;
    const int t     = blockIdx.y & 511;
    const float* bi  = dir ? bih_b : bih_f;
    const float* bh  = dir ? bhh_b : bhh_f;
    const int tsrc   = dir ? (TLEN - 1 - t) : t;

    if (tid < 128) {
        const int gg = gtile * 128 + tid;
        bias_s[tid] = bi[gg] + bh[gg];
    }

    const __half* wsrc = g_wih_h + (size_t)(dir * GDIM + gtile * 128) * EDIM;
    #pragma unroll
    for (int it = 0; it < 8; ++it) {
        const int idx = it * 256 + tid;
        const int rb = idx >> 4, ch = idx & 15;
        const int tok = __ldg(&x[rb * TLEN + tsrc]);
        cpa16(&Esm[rb * PJ_STRIDE + ch * 8], g_table_h + (size_t)tok * EDIM + ch * 8);
    }
    #pragma unroll
    for (int it = 0; it < 8; ++it) {
        const int idx = it * 256 + tid;
        const int rg = idx >> 4, ch = idx & 15;
        cpa16(&Wsm[rg * PJ_STRIDE + ch * 8], wsrc + (size_t)rg * EDIM + ch * 8);
    }
    asm volatile("cp.async.commit_group;");
    asm volatile("cp.async.wait_group 0;" ::: "memory");
    __syncthreads();

    const int li = lane & 7, grp = lane >> 3;
    const int wg = w & 3, wb = w >> 2;
    const int gbase = wg * 32;
    const int row = lane >> 2, kq = (lane & 3) * 2;

    unsigned D[2][8][2];
    #pragma unroll
    for (int m = 0; m < 2; ++m) {
        const unsigned hb0 = dup_h2(bias_s[gbase + m * 16 + row]);
        const unsigned hb1 = dup_h2(bias_s[gbase + m * 16 + row + 8]);
        #pragma unroll
        for (int nt = 0; nt < 8; ++nt) { D[m][nt][0] = hb0; D[m][nt][1] = hb1; }
    }

    #pragma unroll
    for (int p = 0; p < 4; ++p) {
        unsigned A[2][2][4];
        #pragma unroll
        for (int m = 0; m < 2; ++m) {
            const unsigned abase = sptr(Wsm) +
                (((gbase + m * 16 + (grp & 1) * 8 + li) * PJ_STRIDE + (grp >> 1) * 8) << 1);
            ldsm4(A[m][0][0], A[m][0][1], A[m][0][2], A[m][0][3], abase + (2 * p) * 32);
            ldsm4(A[m][1][0], A[m][1][1], A[m][1][2], A[m][1][3], abase + (2 * p + 1) * 32);
        }
        #pragma unroll
        for (int nt = 0; nt < 8; ++nt) {
            unsigned b0a, b1a, b0b, b1b;
            const unsigned eb = sptr(Esm) +
                (((wb * 64 + nt * 8 + li) * PJ_STRIDE + grp * 8) << 1) + p * 64;
            ldsm4(b0a, b1a, b0b, b1b, eb);
            #pragma unroll
            for (int m = 0; m < 2; ++m) {
                mmaf16(D[m][nt][0], D[m][nt][1],
                       A[m][0][0], A[m][0][1], A[m][0][2], A[m][0][3], b0a, b1a);
                mmaf16(D[m][nt][0], D[m][nt][1],
                       A[m][1][0], A[m][1][1], A[m][1][2], A[m][1][3], b0b, b1b);
            }
        }
    }

    __half* base = g_xp + (size_t)(dir * TLEN + t) * 16 * GDIM * 8;
    #pragma unroll
    for (int m = 0; m < 2; ++m) {
        const int g0 = gtile * 128 + gbase + m * 16 + row;
        #pragma unroll
        for (int nt = 0; nt < 8; ++nt) {
            const int slice = wb * 8 + nt;
            __half* o = base + ((size_t)slice * GDIM) * 8 + kq;
            *(unsigned*)(o + (size_t)g0 * 8)       = D[m][nt][0];
            *(unsigned*)(o + (size_t)(g0 + 8) * 8) = D[m][nt][1];
        }
    }
}

// =====================================================================
// Kernel 2: LSTM scan — 16 warps, gate-pair split for SMSP overlap.
// 32 CTAs = 2 dir x 16 slices; 512 thr = 16 warps (4/SMSP).
// Warp w: u-range [16*(w&7),+16); warps 0-7 gates {i,f}, 8-15 {g,o}.
// g,o acts exchanged via 4KB smem; c,h,hmax live in warps 0-7 regs.
// =====================================================================
#define SC_WSTRIDE 136
#define SC_SMEM (512 * SC_WSTRIDE * 2)   // 139264 B dynamic

__global__ void __launch_bounds__(512, 1) scan_kernel(
    const float* __restrict__ Whh_f, const float* __restrict__ Whh_b)
{
    extern __shared__ char dynsm[];
    __half* Wsm = (__half*)dynsm;   // [512][136]
    __shared__ __align__(16) __half h_pp[2][HDIM][8];
    __shared__ __align__(16) unsigned gx[2][HDIM][4];   // [G/O][u][b-pair]

    const int tid  = threadIdx.x, lane = tid & 31, w = tid >> 5;
    const int dir  = blockIdx.x >> 4;
    const int slice = blockIdx.x & 15;
    const float* Whh = dir ? Whh_b : Whh_f;

    // Whh -> fp16 smem (512 rows x 32 float4)
    #pragma unroll 4
    for (int it = 0; it < 32; ++it) {
        const int idx = it * 512 + tid;
        const int rw = idx >> 5, q = idx & 31;
        const float4 v = __ldg((const float4*)(Whh + (size_t)rw * HDIM) + q);
        const __half2 a = __floats2half2_rn(v.x, v.y);
        const __half2 b = __floats2half2_rn(v.z, v.w);
        *(uint2*)&Wsm[rw * SC_WSTRIDE + q * 4] =
            make_uint2(*(const unsigned*)&a, *(const unsigned*)&b);
    }
    for (int i = tid; i < 2 * HDIM * 8; i += 512) ((__half*)h_pp)[i] = __float2half(0.f);
    __syncthreads();

    const int li = lane & 7, grp = lane >> 3;
    const int u0 = (w & 7) * 16;         // u-range base
    const int g0 = (w < 8) ? 0 : 2;      // gate-pair base (i,f) or (g,o)
    const bool is_if = (w < 8);

    // A frags: 2 gates x 8 kt = 64 regs
    unsigned A[2][8][4];
    #pragma unroll
    for (int j = 0; j < 2; ++j) {
        const unsigned base = sptr(Wsm) +
            ((((g0 + j) * 128 + u0 + (grp & 1) * 8 + li) * SC_WSTRIDE + (grp >> 1) * 8) << 1);
        #pragma unroll
        for (int kt = 0; kt < 8; ++kt)
            ldsm4(A[j][kt][0], A[j][kt][1], A[j][kt][2], A[j][kt][3], base + kt * 32);
    }

    const int ur = u0 + (lane >> 2);
    const int cb = (lane & 3) * 2;
    const __half* xpd = g_xp + (size_t)dir * TLEN * 16 * GDIM * 8;
    size_t off[2];
    #pragma unroll
    for (int j = 0; j < 2; ++j)
        off[j] = ((size_t)slice * GDIM + (g0 + j) * 128 + ur) * 8 + cb;

    unsigned px0[2], px1[2];
    #pragma unroll
    for (int j = 0; j < 2; ++j) {
        px0[j] = *(const unsigned*)(xpd + off[j]);
        px1[j] = *(const unsigned*)(xpd + off[j] + 64);
    }

    unsigned c20 = 0u, c21 = 0u;                      // cell state (warps 0-7)
    unsigned hm0 = 0xFC00FC00u, hm1 = 0xFC00FC00u;    // -inf f16x2 running max

    for (int t = 0; t < TLEN; ++t) {
        // B frags from current h
        unsigned B[8][2];
        const unsigned hbase = sptr(&h_pp[t & 1][0][0]) + lane * 16;
        #pragma unroll
        for (int j = 0; j < 4; ++j)
            ldsm4t(B[2*j][0], B[2*j][1], B[2*j+1][0], B[2*j+1][1], hbase + j * 512);

        unsigned D[2][2];
        #pragma unroll
        for (int j = 0; j < 2; ++j) { D[j][0] = px0[j]; D[j][1] = px1[j]; }

        // prefetch next xp
        const __half* xn = xpd + (size_t)((t + 1 < TLEN) ? t + 1 : t) * 16 * GDIM * 8;
        #pragma unroll
        for (int j = 0; j < 2; ++j) {
            px0[j] = *(const unsigned*)(xn + off[j]);
            px1[j] = *(const unsigned*)(xn + off[j] + 64);
        }

        // 16 mma: 2 independent 8-deep chains
        #pragma unroll
        for (int kt = 0; kt < 8; ++kt) {
            mmaf16(D[0][0], D[0][1],
                   A[0][kt][0], A[0][kt][1], A[0][kt][2], A[0][kt][3], B[kt][0], B[kt][1]);
            mmaf16(D[1][0], D[1][1],
                   A[1][kt][0], A[1][kt][1], A[1][kt][2], A[1][kt][3], B[kt][0], B[kt][1]);
        }

        unsigned V00, V01, V10, V11;   // gate0:(u,u+8) gate1:(u,u+8)
        if (is_if) {
            V00 = hsig2(D[0][0]); V01 = hsig2(D[0][1]);     // i
            V10 = hsig2(D[1][0]); V11 = hsig2(D[1][1]);     // f
        } else {
            V00 = htanh2(D[0][0]); V01 = htanh2(D[0][1]);   // g
            V10 = hsig2(D[1][0]);  V11 = hsig2(D[1][1]);    // o
            gx[0][ur][lane & 3]     = V00;
            gx[0][ur + 8][lane & 3] = V01;
            gx[1][ur][lane & 3]     = V10;
            gx[1][ur + 8][lane & 3] = V11;
        }
        __syncthreads();

        if (is_if) {
            const unsigned G0 = gx[0][ur][lane & 3], G1 = gx[0][ur + 8][lane & 3];
            const unsigned O0 = gx[1][ur][lane & 3], O1 = gx[1][ur + 8][lane & 3];
            c20 = hfma2(V10, c20, hmul2(V00, G0));
            c21 = hfma2(V11, c21, hmul2(V01, G1));
            const unsigned H0 = hmul2(O0, htanh2(c20));
            const unsigned H1 = hmul2(O1, htanh2(c21));
            hm0 = hmax2u(hm0, H0);
            hm1 = hmax2u(hm1, H1);
            __half* hw = &h_pp[(t + 1) & 1][0][0];
            *(unsigned*)&hw[ur * 8 + cb]       = H0;
            *(unsigned*)&hw[(ur + 8) * 8 + cb] = H1;
        }
        __syncthreads();
    }

    if (is_if) {
        const float2 m0 = h22f2(hm0), m1 = h22f2(hm1);
        const int bb = slice * 8;
        g_pool[((size_t)dir * BATCH + bb + cb)     * HDIM + ur]     = m0.x;
        g_pool[((size_t)dir * BATCH + bb + cb + 1) * HDIM + ur]     = m0.y;
        g_pool[((size_t)dir * BATCH + bb + cb)     * HDIM + ur + 8] = m1.x;
        g_pool[((size_t)dir * BATCH + bb + cb + 1) * HDIM + ur + 8] = m1.y;
    }
}

// =====================================================================
// Kernel 3: MLP head.
// =====================================================================
__global__ void __launch_bounds__(64) mlp_kernel(
    const float* __restrict__ W1, const float* __restrict__ b1,
    const float* __restrict__ W2, const float* __restrict__ b2,
    float* __restrict__ out)
{
    __shared__ __align__(16) float pv[256];
    __shared__ float red[64];
    const int b = blockIdx.x;
    const int j = threadIdx.x;

    for (int k = j; k < 256; k += 64) {
        const int dir = k >> 7, u = k & 127;
        pv[k] = g_pool[((size_t)dir * BATCH + b) * HDIM + u];
    }
    __syncthreads();

    float acc = b1[j];
    const float4* w4 = (const float4*)(W1 + (size_t)j * 256);
    const float4* p4 = (const float4*)pv;
    #pragma unroll 8
    for (int k = 0; k < 64; ++k) {
        const float4 wv = w4[k], p = p4[k];
        acc += wv.x * p.x + wv.y * p.y + wv.z * p.z + wv.w * p.w;
    }
    red[j] = fmaxf(acc, 0.f) * W2[j];
    __syncthreads();

    if (j == 0) {
        float s = b2[0];
        #pragma unroll
        for (int k = 0; k < 64; ++k) s += red[k];
        out[b] = 1.f / (1.f + expf(-s));
    }
}

// =====================================================================
extern "C" void kernel_launch(void* const* d_in, const int* in_sizes, int n_in,
                              void* d_out, int out_size) {
    const int*   x     = (const int*)d_in[0];
    const float* table = (const float*)d_in[1];
    const float* Wih_f = (const float*)d_in[2];
    const float* Whh_f = (const float*)d_in[3];
    const float* bih_f = (const float*)d_in[4];
    const float* bhh_f = (const float*)d_in[5];
    const float* Wih_b = (const float*)d_in[6];
    const float* Whh_b = (const float*)d_in[7];
    const float* bih_b = (const float*)d_in[8];
    const float* bhh_b = (const float*)d_in[9];
    const float* W1    = (const float*)d_in[10];
    const float* b1    = (const float*)d_in[11];
    const float* W2    = (const float*)d_in[12];
    const float* b2    = (const float*)d_in[13];
    float* out = (float*)d_out;

    cudaFuncSetAttribute(proj_kernel, cudaFuncAttributeMaxDynamicSharedMemorySize, PJ_SMEM);
    cudaFuncSetAttribute(scan_kernel, cudaFuncAttributeMaxDynamicSharedMemorySize, SC_SMEM);

    conv_table_kernel<<<(VOCAB * EDIM) / (256 * 4), 256>>>(table);
    conv_wih_kernel<<<(GDIM * EDIM) / (256 * 4), 256>>>(Wih_f, Wih_b);

    dim3 pg(4, 2 * TLEN);
    proj_kernel<<<pg, 256, PJ_SMEM>>>(x, bih_f, bhh_f, bih_b, bhh_b);
    scan_kernel<<<32, 512, SC_SMEM>>>(Whh_f, Whh_b);
    mlp_kernel<<<128, 64>>>(W1, b1, W2, b2, out);
}

// round 12
// speedup vs baseline: 1.1451x; 1.1451x over previous
#include <cuda_runtime.h>
#include <cuda_fp16.h>
#include <cstdint>
#include <cstddef>

#define TLEN  512
#define BATCH 128
#define EDIM  128
#define HDIM  128
#define GDIM  512   // 4*H
#define VOCAB 100000

// Scratch (device globals — no allocation).
// xp layout: [dir][t][slice(16)][g(512)][8b]  fp16
static __device__ __half g_xp[(size_t)2 * TLEN * 16 * GDIM * 8];
static __device__ __align__(16) __half g_table_h[(size_t)VOCAB * EDIM];
static __device__ __align__(16) __half g_wih_h[2 * GDIM * EDIM];
static __device__ float g_pool[2 * BATCH * HDIM];
static __device__ int   g_flagc[2][TLEN / 4];   // proj completion, 16 tiles per 4-t chunk

// ---------- helpers ----------
#define H_HALF2 0x38003800u   // {0.5,0.5} fp16
__device__ __forceinline__ unsigned hmul2(unsigned a, unsigned b) {
    unsigned d; asm("mul.rn.f16x2 %0,%1,%2;" : "=r"(d) : "r"(a), "r"(b)); return d;
}
__device__ __forceinline__ unsigned hadd2u(unsigned a, unsigned b) {
    unsigned d; asm("add.rn.f16x2 %0,%1,%2;" : "=r"(d) : "r"(a), "r"(b)); return d;
}
__device__ __forceinline__ unsigned hfma2(unsigned a, unsigned b, unsigned c) {
    unsigned d; asm("fma.rn.f16x2 %0,%1,%2,%3;" : "=r"(d) : "r"(a), "r"(b), "r"(c)); return d;
}
__device__ __forceinline__ unsigned htanh2(unsigned a) {
    unsigned d; asm("tanh.approx.f16x2 %0,%1;" : "=r"(d) : "r"(a)); return d;
}
__device__ __forceinline__ unsigned hsig2(unsigned x) {   // 0.5*tanh(0.5x)+0.5
    return hfma2(htanh2(hmul2(x, H_HALF2)), H_HALF2, H_HALF2);
}
__device__ __forceinline__ unsigned hmax2u(unsigned a, unsigned b) {
    __half2 r = __hmax2(*(__half2*)&a, *(__half2*)&b);
    return *(unsigned*)&r;
}
__device__ __forceinline__ float2 h22f2(unsigned v) {
    return __half22float2(*(__half2*)&v);
}
__device__ __forceinline__ unsigned dup_h2(float v) {
    __half2 h = __half2half2(__float2half_rn(v));
    return *(unsigned*)&h;
}
__device__ __forceinline__ unsigned sptr(const void* p) {
    return (unsigned)__cvta_generic_to_shared(p);
}
__device__ __forceinline__ void cpa16(void* s, const void* g) {
    asm volatile("cp.async.cg.shared.global [%0], [%1], 16;" :: "r"(sptr(s)), "l"(g));
}
__device__ __forceinline__ int ld_acq(const int* p) {
    int v; asm volatile("ld.acquire.gpu.global.s32 %0,[%1];" : "=r"(v) : "l"(p)); return v;
}
__device__ __forceinline__ void mmaf16(unsigned& d0, unsigned& d1,
                                       unsigned a0, unsigned a1, unsigned a2, unsigned a3,
                                       unsigned b0, unsigned b1) {
    asm("mma.sync.aligned.m16n8k16.row.col.f16.f16.f16.f16 "
        "{%0,%1},{%2,%3,%4,%5},{%6,%7},{%0,%1};"
        : "+r"(d0), "+r"(d1)
        : "r"(a0), "r"(a1), "r"(a2), "r"(a3), "r"(b0), "r"(b1));
}
__device__ __forceinline__ void ldsm4(unsigned& r0, unsigned& r1, unsigned& r2, unsigned& r3,
                                      unsigned addr) {
    asm volatile("ldmatrix.sync.aligned.m8n8.x4.shared.b16 {%0,%1,%2,%3}, [%4];"
                 : "=r"(r0), "=r"(r1), "=r"(r2), "=r"(r3) : "r"(addr));
}
__device__ __forceinline__ void ldsm4t(unsigned& r0, unsigned& r1, unsigned& r2, unsigned& r3,
                                       unsigned addr) {
    asm volatile("ldmatrix.sync.aligned.m8n8.x4.trans.shared.b16 {%0,%1,%2,%3}, [%4];"
                 : "=r"(r0), "=r"(r1), "=r"(r2), "=r"(r3) : "r"(addr));
}

// =====================================================================
// Kernel 0a/0b: one-time fp32 -> fp16 conversions + flag reset
// =====================================================================
__global__ void __launch_bounds__(256) conv_table_kernel(const float* __restrict__ t) {
    const size_t i = ((size_t)blockIdx.x * 256 + threadIdx.x) * 4;
    const float4 v = *(const float4*)(t + i);
    const __half2 a = __floats2half2_rn(v.x, v.y);
    const __half2 b = __floats2half2_rn(v.z, v.w);
    *(uint2*)&g_table_h[i] = make_uint2(*(const unsigned*)&a, *(const unsigned*)&b);
}
__global__ void __launch_bounds__(256) conv_wih_kernel(const float* __restrict__ wf,
                                                       const float* __restrict__ wb) {
    if (blockIdx.x == 0 && threadIdx.x < 256)
        ((int*)g_flagc)[threadIdx.x] = 0;              // reset 2*128 counters
    const int i = (blockIdx.x * 256 + threadIdx.x) * 4;
    {
        const float4 v = *(const float4*)(wf + i);
        const __half2 a = __floats2half2_rn(v.x, v.y);
        const __half2 b = __floats2half2_rn(v.z, v.w);
        *(uint2*)&g_wih_h[i] = make_uint2(*(const unsigned*)&a, *(const unsigned*)&b);
    }
    {
        const float4 v = *(const float4*)(wb + i);
        const __half2 a = __floats2half2_rn(v.x, v.y);
        const __half2 b = __floats2half2_rn(v.z, v.w);
        *(uint2*)&g_wih_h[GDIM * EDIM + i] = make_uint2(*(const unsigned*)&a, *(const unsigned*)&b);
    }
}

// =====================================================================
// MEGA kernel: blocks 0-31 = persistent scan CTAs (2 dir x 16 slices);
// blocks 32..4127 = proj tiles, t-major with dirs interleaved so xp is
// produced in ascending-t order ~3x faster than the scan consumes it.
// =====================================================================
#define PJ_STRIDE 136
#define SC_WSTRIDE 136
#define SC_SMEM (512 * SC_WSTRIDE * 2)   // 139264 B dynamic (covers proj's 69632 too)

__global__ void __launch_bounds__(256, 1) mega_kernel(
    const int* __restrict__ x,
    const float* __restrict__ Whh_f, const float* __restrict__ Whh_b,
    const float* __restrict__ bih_f, const float* __restrict__ bhh_f,
    const float* __restrict__ bih_b, const float* __restrict__ bhh_b)
{
    extern __shared__ char dynsm[];
    const int tid = threadIdx.x, lane = tid & 31, w = tid >> 5;
    const int bid = blockIdx.x;

    if (bid >= 32) {
        // ================= PROJ ROLE =================
        __half* Wsm = (__half*)dynsm;             // [128][136]
        __half* Esm = Wsm + 128 * PJ_STRIDE;      // [128][136]
        __shared__ float bias_s[128];

        const int pbid  = bid - 32;
        const int gtile = pbid & 3;
        const int tt    = pbid >> 2;
        const int dir   = tt & 1;                 // dirs interleaved, t ascending
        const int t     = tt >> 1;
        const float* bi = dir ? bih_b : bih_f;
        const float* bh = dir ? bhh_b : bhh_f;
        const int tsrc  = dir ? (TLEN - 1 - t) : t;

        if (tid < 128) {
            const int gg = gtile * 128 + tid;
            bias_s[tid] = bi[gg] + bh[gg];
        }

        const __half* wsrc = g_wih_h + (size_t)(dir * GDIM + gtile * 128) * EDIM;
        #pragma unroll
        for (int it = 0; it < 8; ++it) {
            const int idx = it * 256 + tid;
            const int rb = idx >> 4, ch = idx & 15;
            const int tok = __ldg(&x[rb * TLEN + tsrc]);
            cpa16(&Esm[rb * PJ_STRIDE + ch * 8], g_table_h + (size_t)tok * EDIM + ch * 8);
        }
        #pragma unroll
        for (int it = 0; it < 8; ++it) {
            const int idx = it * 256 + tid;
            const int rg = idx >> 4, ch = idx & 15;
            cpa16(&Wsm[rg * PJ_STRIDE + ch * 8], wsrc + (size_t)rg * EDIM + ch * 8);
        }
        asm volatile("cp.async.commit_group;");
        asm volatile("cp.async.wait_group 0;" ::: "memory");
        __syncthreads();

        const int li = lane & 7, grp = lane >> 3;
        const int wg = w & 3, wb = w >> 2;
        const int gbase = wg * 32;
        const int row = lane >> 2, kq = (lane & 3) * 2;

        unsigned D[2][8][2];
        #pragma unroll
        for (int m = 0; m < 2; ++m) {
            const unsigned hb0 = dup_h2(bias_s[gbase + m * 16 + row]);
            const unsigned hb1 = dup_h2(bias_s[gbase + m * 16 + row + 8]);
            #pragma unroll
            for (int nt = 0; nt < 8; ++nt) { D[m][nt][0] = hb0; D[m][nt][1] = hb1; }
        }

        #pragma unroll
        for (int p = 0; p < 4; ++p) {
            unsigned A[2][2][4];
            #pragma unroll
            for (int m = 0; m < 2; ++m) {
                const unsigned abase = sptr(Wsm) +
                    (((gbase + m * 16 + (grp & 1) * 8 + li) * PJ_STRIDE + (grp >> 1) * 8) << 1);
                ldsm4(A[m][0][0], A[m][0][1], A[m][0][2], A[m][0][3], abase + (2 * p) * 32);
                ldsm4(A[m][1][0], A[m][1][1], A[m][1][2], A[m][1][3], abase + (2 * p + 1) * 32);
            }
            #pragma unroll
            for (int nt = 0; nt < 8; ++nt) {
                unsigned b0a, b1a, b0b, b1b;
                const unsigned eb = sptr(Esm) +
                    (((wb * 64 + nt * 8 + li) * PJ_STRIDE + grp * 8) << 1) + p * 64;
                ldsm4(b0a, b1a, b0b, b1b, eb);
                #pragma unroll
                for (int m = 0; m < 2; ++m) {
                    mmaf16(D[m][nt][0], D[m][nt][1],
                           A[m][0][0], A[m][0][1], A[m][0][2], A[m][0][3], b0a, b1a);
                    mmaf16(D[m][nt][0], D[m][nt][1],
                           A[m][1][0], A[m][1][1], A[m][1][2], A[m][1][3], b0b, b1b);
                }
            }
        }

        __half* base = g_xp + (size_t)(dir * TLEN + t) * 16 * GDIM * 8;
        #pragma unroll
        for (int m = 0; m < 2; ++m) {
            const int gg0 = gtile * 128 + gbase + m * 16 + row;
            #pragma unroll
            for (int nt = 0; nt < 8; ++nt) {
                const int slice = wb * 8 + nt;
                __half* o = base + ((size_t)slice * GDIM) * 8 + kq;
                *(unsigned*)(o + (size_t)gg0 * 8)       = D[m][nt][0];
                *(unsigned*)(o + (size_t)(gg0 + 8) * 8) = D[m][nt][1];
            }
        }

        // completion signal: all stores visible, then count this tile
        __threadfence();
        __syncthreads();
        if (tid == 0) atomicAdd(&g_flagc[dir][t >> 2], 1);
        return;
    }

    // ================= SCAN ROLE (R9 structure + flag gating) =================
    {
        __half* Wsm = (__half*)dynsm;   // [512][136]
        __shared__ __align__(16) __half h_pp[2][HDIM][8];

        const int dir   = bid >> 4;
        const int slice = bid & 15;
        const float* Whh = dir ? Whh_b : Whh_f;

        #pragma unroll 4
        for (int it = 0; it < 64; ++it) {
            const int idx = it * 256 + tid;
            const int rw = idx >> 5, q = idx & 31;
            const float4 v = __ldg((const float4*)(Whh + (size_t)rw * HDIM) + q);
            const __half2 a = __floats2half2_rn(v.x, v.y);
            const __half2 b = __floats2half2_rn(v.z, v.w);
            *(uint2*)&Wsm[rw * SC_WSTRIDE + q * 4] =
                make_uint2(*(const unsigned*)&a, *(const unsigned*)&b);
        }
        for (int i = tid; i < 2 * HDIM * 8; i += 256) ((__half*)h_pp)[i] = __float2half(0.f);
        __syncthreads();

        const int li = lane & 7, grp = lane >> 3;
        unsigned A[4][8][4];
        #pragma unroll
        for (int q = 0; q < 4; ++q) {
            const unsigned base = sptr(Wsm) +
                (((q * 128 + w * 16 + (grp & 1) * 8 + li) * SC_WSTRIDE + (grp >> 1) * 8) << 1);
            #pragma unroll
            for (int kt = 0; kt < 8; ++kt)
                ldsm4(A[q][kt][0], A[q][kt][1], A[q][kt][2], A[q][kt][3], base + kt * 32);
        }

        const int ur = w * 16 + (lane >> 2);
        const int cb = (lane & 3) * 2;
        const __half* xpd = g_xp + (size_t)dir * TLEN * 16 * GDIM * 8;
        size_t off[4];
        #pragma unroll
        for (int q = 0; q < 4; ++q)
            off[q] = ((size_t)slice * GDIM + q * 128 + ur) * 8 + cb;

        // wait for chunk 0 (covers t=0..3) before first xp loads
        while (ld_acq(&g_flagc[dir][0]) < 16) __nanosleep(200);

        unsigned px0[4], px1[4];
        #pragma unroll
        for (int q = 0; q < 4; ++q) {
            px0[q] = *(const unsigned*)(xpd + off[q]);
            px1[q] = *(const unsigned*)(xpd + off[q] + 64);
        }

        unsigned c20 = 0u, c21 = 0u;
        unsigned hm0 = 0xFC00FC00u, hm1 = 0xFC00FC00u;

        for (int t = 0; t < TLEN; ++t) {
            // every 4th step, gate the NEXT chunk (covers prefetches t+1..t+4)
            if ((t & 3) == 0 && (t >> 2) + 1 < TLEN / 4) {
                const int* fp = &g_flagc[dir][(t >> 2) + 1];
                while (ld_acq(fp) < 16) __nanosleep(200);
            }

            unsigned B[8][2];
            const unsigned hbase = sptr(&h_pp[t & 1][0][0]) + lane * 16;
            #pragma unroll
            for (int j = 0; j < 4; ++j)
                ldsm4t(B[2*j][0], B[2*j][1], B[2*j+1][0], B[2*j+1][1], hbase + j * 512);

            unsigned D[4][2], E[4][2];
            #pragma unroll
            for (int q = 0; q < 4; ++q) {
                D[q][0] = px0[q]; D[q][1] = px1[q];
                E[q][0] = 0u;     E[q][1] = 0u;
            }

            const __half* xn = xpd + (size_t)((t + 1 < TLEN) ? t + 1 : t) * 16 * GDIM * 8;
            #pragma unroll
            for (int q = 0; q < 4; ++q) {
                px0[q] = *(const unsigned*)(xn + off[q]);
                px1[q] = *(const unsigned*)(xn + off[q] + 64);
            }

            #pragma unroll
            for (int kt = 0; kt < 4; ++kt) {
                #pragma unroll
                for (int q = 0; q < 4; ++q) {
                    mmaf16(D[q][0], D[q][1],
                           A[q][kt][0], A[q][kt][1], A[q][kt][2], A[q][kt][3],
                           B[kt][0], B[kt][1]);
                    mmaf16(E[q][0], E[q][1],
                           A[q][kt+4][0], A[q][kt+4][1], A[q][kt+4][2], A[q][kt+4][3],
                           B[kt+4][0], B[kt+4][1]);
                }
            }
            unsigned P[4][2];
            #pragma unroll
            for (int q = 0; q < 4; ++q) {
                P[q][0] = hadd2u(D[q][0], E[q][0]);
                P[q][1] = hadd2u(D[q][1], E[q][1]);
            }

            const unsigned I0 = hsig2(P[0][0]),  I1 = hsig2(P[0][1]);
            const unsigned F0 = hsig2(P[1][0]),  F1 = hsig2(P[1][1]);
            const unsigned G0 = htanh2(P[2][0]), G1 = htanh2(P[2][1]);
            const unsigned O0 = hsig2(P[3][0]),  O1 = hsig2(P[3][1]);

            c20 = hfma2(F0, c20, hmul2(I0, G0));
            c21 = hfma2(F1, c21, hmul2(I1, G1));
            const unsigned H0 = hmul2(O0, htanh2(c20));
            const unsigned H1 = hmul2(O1, htanh2(c21));
            hm0 = hmax2u(hm0, H0);
            hm1 = hmax2u(hm1, H1);

            __half* hw = &h_pp[(t + 1) & 1][0][0];
            *(unsigned*)&hw[ur * 8 + cb]       = H0;
            *(unsigned*)&hw[(ur + 8) * 8 + cb] = H1;
            __syncthreads();
        }

        const float2 m0 = h22f2(hm0), m1 = h22f2(hm1);
        const int bb = slice * 8;
        g_pool[((size_t)dir * BATCH + bb + cb)     * HDIM + ur]     = m0.x;
        g_pool[((size_t)dir * BATCH + bb + cb + 1) * HDIM + ur]     = m0.y;
        g_pool[((size_t)dir * BATCH + bb + cb)     * HDIM + ur + 8] = m1.x;
        g_pool[((size_t)dir * BATCH + bb + cb + 1) * HDIM + ur + 8] = m1.y;
    }
}

// =====================================================================
// Kernel 3: MLP head.
// =====================================================================
__global__ void __launch_bounds__(64) mlp_kernel(
    const float* __restrict__ W1, const float* __restrict__ b1,
    const float* __restrict__ W2, const float* __restrict__ b2,
    float* __restrict__ out)
{
    __shared__ __align__(16) float pv[256];
    __shared__ float red[64];
    const int b = blockIdx.x;
    const int j = threadIdx.x;

    for (int k = j; k < 256; k += 64) {
        const int dir = k >> 7, u = k & 127;
        pv[k] = g_pool[((size_t)dir * BATCH + b) * HDIM + u];
    }
    __syncthreads();

    float acc = b1[j];
    const float4* w4 = (const float4*)(W1 + (size_t)j * 256);
    const float4* p4 = (const float4*)pv;
    #pragma unroll 8
    for (int k = 0; k < 64; ++k) {
        const float4 wv = w4[k], p = p4[k];
        acc += wv.x * p.x + wv.y * p.y + wv.z * p.z + wv.w * p.w;
    }
    red[j] = fmaxf(acc, 0.f) * W2[j];
    __syncthreads();

    if (j == 0) {
        float s = b2[0];
        #pragma unroll
        for (int k = 0; k < 64; ++k) s += red[k];
        out[b] = 1.f / (1.f + expf(-s));
    }
}

// =====================================================================
extern "C" void kernel_launch(void* const* d_in, const int* in_sizes, int n_in,
                              void* d_out, int out_size) {
    const int*   x     = (const int*)d_in[0];
    const float* table = (const float*)d_in[1];
    const float* Wih_f = (const float*)d_in[2];
    const float* Whh_f = (const float*)d_in[3];
    const float* bih_f = (const float*)d_in[4];
    const float* bhh_f = (const float*)d_in[5];
    const float* Wih_b = (const float*)d_in[6];
    const float* Whh_b = (const float*)d_in[7];
    const float* bih_b = (const float*)d_in[8];
    const float* bhh_b = (const float*)d_in[9];
    const float* W1    = (const float*)d_in[10];
    const float* b1    = (const float*)d_in[11];
    const float* W2    = (const float*)d_in[12];
    const float* b2    = (const float*)d_in[13];
    float* out = (float*)d_out;

    cudaFuncSetAttribute(mega_kernel, cudaFuncAttributeMaxDynamicSharedMemorySize, SC_SMEM);

    conv_table_kernel<<<(VOCAB * EDIM) / (256 * 4), 256>>>(table);
    conv_wih_kernel<<<(GDIM * EDIM) / (256 * 4), 256>>>(Wih_f, Wih_b);

    mega_kernel<<<32 + 4096, 256, SC_SMEM>>>(x, Whh_f, Whh_b,
                                             bih_f, bhh_f, bih_b, bhh_b);
    mlp_kernel<<<128, 64>>>(W1, b1, W2, b2, out);
}

// round 13
// speedup vs baseline: 1.3751x; 1.2009x over previous
#include <cuda_runtime.h>
#include <cuda_fp16.h>
#include <cstdint>
#include <cstddef>

#define TLEN  512
#define BATCH 128
#define EDIM  128
#define HDIM  128
#define GDIM  512   // 4*H
#define VOCAB 100000

// Scratch (device globals — no allocation).
// xp layout: [dir][t][slice(16)][g(512)][8b]  fp16
static __device__ __half g_xp[(size_t)2 * TLEN * 16 * GDIM * 8];
static __device__ __align__(16) __half g_wih_h[2 * GDIM * EDIM];
static __device__ float g_pool[2 * BATCH * HDIM];
static __device__ int   g_flagc[2][TLEN / 4];   // proj completion, 16 tiles per 4-t chunk
static __device__ int   g_prog[2];              // scan progress (chunk index), per dir

// ---------- helpers ----------
#define H_HALF2 0x38003800u   // {0.5,0.5} fp16
__device__ __forceinline__ unsigned hmul2(unsigned a, unsigned b) {
    unsigned d; asm("mul.rn.f16x2 %0,%1,%2;" : "=r"(d) : "r"(a), "r"(b)); return d;
}
__device__ __forceinline__ unsigned hadd2u(unsigned a, unsigned b) {
    unsigned d; asm("add.rn.f16x2 %0,%1,%2;" : "=r"(d) : "r"(a), "r"(b)); return d;
}
__device__ __forceinline__ unsigned hfma2(unsigned a, unsigned b, unsigned c) {
    unsigned d; asm("fma.rn.f16x2 %0,%1,%2,%3;" : "=r"(d) : "r"(a), "r"(b), "r"(c)); return d;
}
__device__ __forceinline__ unsigned htanh2(unsigned a) {
    unsigned d; asm("tanh.approx.f16x2 %0,%1;" : "=r"(d) : "r"(a)); return d;
}
__device__ __forceinline__ unsigned hsig2(unsigned x) {   // 0.5*tanh(0.5x)+0.5
    return hfma2(htanh2(hmul2(x, H_HALF2)), H_HALF2, H_HALF2);
}
__device__ __forceinline__ unsigned hmax2u(unsigned a, unsigned b) {
    __half2 r = __hmax2(*(__half2*)&a, *(__half2*)&b);
    return *(unsigned*)&r;
}
__device__ __forceinline__ float2 h22f2(unsigned v) {
    return __half22float2(*(__half2*)&v);
}
__device__ __forceinline__ unsigned dup_h2(float v) {
    __half2 h = __half2half2(__float2half_rn(v));
    return *(unsigned*)&h;
}
__device__ __forceinline__ unsigned sptr(const void* p) {
    return (unsigned)__cvta_generic_to_shared(p);
}
__device__ __forceinline__ void cpa16(void* s, const void* g) {
    asm volatile("cp.async.cg.shared.global [%0], [%1], 16;" :: "r"(sptr(s)), "l"(g));
}
__device__ __forceinline__ int ld_acq(const int* p) {
    int v; asm volatile("ld.acquire.gpu.global.s32 %0,[%1];" : "=r"(v) : "l"(p)); return v;
}
__device__ __forceinline__ int ld_vol(const int* p) { return *(volatile const int*)p; }
__device__ __forceinline__ void mmaf16(unsigned& d0, unsigned& d1,
                                       unsigned a0, unsigned a1, unsigned a2, unsigned a3,
                                       unsigned b0, unsigned b1) {
    asm("mma.sync.aligned.m16n8k16.row.col.f16.f16.f16.f16 "
        "{%0,%1},{%2,%3,%4,%5},{%6,%7},{%0,%1};"
        : "+r"(d0), "+r"(d1)
        : "r"(a0), "r"(a1), "r"(a2), "r"(a3), "r"(b0), "r"(b1));
}
__device__ __forceinline__ void ldsm4(unsigned& r0, unsigned& r1, unsigned& r2, unsigned& r3,
                                      unsigned addr) {
    asm volatile("ldmatrix.sync.aligned.m8n8.x4.shared.b16 {%0,%1,%2,%3}, [%4];"
                 : "=r"(r0), "=r"(r1), "=r"(r2), "=r"(r3) : "r"(addr));
}
__device__ __forceinline__ void ldsm4t(unsigned& r0, unsigned& r1, unsigned& r2, unsigned& r3,
                                       unsigned addr) {
    asm volatile("ldmatrix.sync.aligned.m8n8.x4.trans.shared.b16 {%0,%1,%2,%3}, [%4];"
                 : "=r"(r0), "=r"(r1), "=r"(r2), "=r"(r3) : "r"(addr));
}

// =====================================================================
// Kernel 0: Wih fp32->fp16 + flag/progress reset (tiny, ~2us)
// =====================================================================
__global__ void __launch_bounds__(256) conv_wih_kernel(const float* __restrict__ wf,
                                                       const float* __restrict__ wb) {
    if (blockIdx.x == 0) {
        if (threadIdx.x < 256) ((int*)g_flagc)[threadIdx.x] = 0;
        if (threadIdx.x < 2)   g_prog[threadIdx.x] = 0;
    }
    const int i = (blockIdx.x * 256 + threadIdx.x) * 4;
    {
        const float4 v = *(const float4*)(wf + i);
        const __half2 a = __floats2half2_rn(v.x, v.y);
        const __half2 b = __floats2half2_rn(v.z, v.w);
        *(uint2*)&g_wih_h[i] = make_uint2(*(const unsigned*)&a, *(const unsigned*)&b);
    }
    {
        const float4 v = *(const float4*)(wb + i);
        const __half2 a = __floats2half2_rn(v.x, v.y);
        const __half2 b = __floats2half2_rn(v.z, v.w);
        *(uint2*)&g_wih_h[GDIM * EDIM + i] = make_uint2(*(const unsigned*)&a, *(const unsigned*)&b);
    }
}

// =====================================================================
// MEGA kernel: blocks 0-31 = persistent scan CTAs (2 dir x 16 slices);
// blocks 32..4127 = proj tiles (t-major, dirs interleaved), rate-limited
// to <= 8 chunks ahead of the scan to keep clocks high / HBM quiet.
// =====================================================================
#define PJ_STRIDE 136
#define SC_WSTRIDE 136
#define SC_SMEM (512 * SC_WSTRIDE * 2)   // 139264 B dynamic (covers proj's 69632 too)

__global__ void __launch_bounds__(256, 1) mega_kernel(
    const int* __restrict__ x, const float* __restrict__ table,
    const float* __restrict__ Whh_f, const float* __restrict__ Whh_b,
    const float* __restrict__ bih_f, const float* __restrict__ bhh_f,
    const float* __restrict__ bih_b, const float* __restrict__ bhh_b)
{
    extern __shared__ char dynsm[];
    const int tid = threadIdx.x, lane = tid & 31, w = tid >> 5;
    const int bid = blockIdx.x;

    if (bid >= 32) {
        // ================= PROJ ROLE =================
        __half* Wsm = (__half*)dynsm;             // [128][136]
        __half* Esm = Wsm + 128 * PJ_STRIDE;      // [128][136]
        __shared__ float bias_s[128];
        __shared__ int   tok_s[128];

        const int pbid  = bid - 32;
        const int gtile = pbid & 3;
        const int tt    = pbid >> 2;
        const int dir   = tt & 1;                 // dirs interleaved, t ascending
        const int t     = tt >> 1;
        const float* bi = dir ? bih_b : bih_f;
        const float* bh = dir ? bhh_b : bhh_f;
        const int tsrc  = dir ? (TLEN - 1 - t) : t;

        // backpressure: stay <= 8 chunks ahead of this dir's scan
        if (tid == 0) {
            const int chunk = t >> 2;
            while (chunk > ld_vol(&g_prog[dir]) + 8) __nanosleep(1000);
        }
        __syncthreads();

        if (tid < 128) {
            const int gg = gtile * 128 + tid;
            bias_s[tid] = bi[gg] + bh[gg];
            tok_s[tid] = x[tid * TLEN + tsrc];
        }

        // W rows via cp.async (pre-converted f16), issued before token sync
        const __half* wsrc = g_wih_h + (size_t)(dir * GDIM + gtile * 128) * EDIM;
        #pragma unroll
        for (int it = 0; it < 8; ++it) {
            const int idx = it * 256 + tid;
            const int rg = idx >> 4, ch = idx & 15;
            cpa16(&Wsm[rg * PJ_STRIDE + ch * 8], wsrc + (size_t)rg * EDIM + ch * 8);
        }
        asm volatile("cp.async.commit_group;");
        __syncthreads();   // tok_s ready

        // E rows: gather f32 table directly, convert inline
        #pragma unroll
        for (int it = 0; it < 16; ++it) {
            const int idx = it * 256 + tid;
            const int rb = idx >> 5, q = idx & 31;
            const float4 v = __ldg((const float4*)(table + (size_t)tok_s[rb] * EDIM) + q);
            const __half2 a = __floats2half2_rn(v.x, v.y);
            const __half2 b = __floats2half2_rn(v.z, v.w);
            *(uint2*)&Esm[rb * PJ_STRIDE + q * 4] =
                make_uint2(*(const unsigned*)&a, *(const unsigned*)&b);
        }
        asm volatile("cp.async.wait_group 0;" ::: "memory");
        __syncthreads();

        const int li = lane & 7, grp = lane >> 3;
        const int wg = w & 3, wb = w >> 2;
        const int gbase = wg * 32;
        const int row = lane >> 2, kq = (lane & 3) * 2;

        unsigned D[2][8][2];
        #pragma unroll
        for (int m = 0; m < 2; ++m) {
            const unsigned hb0 = dup_h2(bias_s[gbase + m * 16 + row]);
            const unsigned hb1 = dup_h2(bias_s[gbase + m * 16 + row + 8]);
            #pragma unroll
            for (int nt = 0; nt < 8; ++nt) { D[m][nt][0] = hb0; D[m][nt][1] = hb1; }
        }

        #pragma unroll
        for (int p = 0; p < 4; ++p) {
            unsigned A[2][2][4];
            #pragma unroll
            for (int m = 0; m < 2; ++m) {
                const unsigned abase = sptr(Wsm) +
                    (((gbase + m * 16 + (grp & 1) * 8 + li) * PJ_STRIDE + (grp >> 1) * 8) << 1);
                ldsm4(A[m][0][0], A[m][0][1], A[m][0][2], A[m][0][3], abase + (2 * p) * 32);
                ldsm4(A[m][1][0], A[m][1][1], A[m][1][2], A[m][1][3], abase + (2 * p + 1) * 32);
            }
            #pragma unroll
            for (int nt = 0; nt < 8; ++nt) {
                unsigned b0a, b1a, b0b, b1b;
                const unsigned eb = sptr(Esm) +
                    (((wb * 64 + nt * 8 + li) * PJ_STRIDE + grp * 8) << 1) + p * 64;
                ldsm4(b0a, b1a, b0b, b1b, eb);
                #pragma unroll
                for (int m = 0; m < 2; ++m) {
                    mmaf16(D[m][nt][0], D[m][nt][1],
                           A[m][0][0], A[m][0][1], A[m][0][2], A[m][0][3], b0a, b1a);
                    mmaf16(D[m][nt][0], D[m][nt][1],
                           A[m][1][0], A[m][1][1], A[m][1][2], A[m][1][3], b0b, b1b);
                }
            }
        }

        __half* base = g_xp + (size_t)(dir * TLEN + t) * 16 * GDIM * 8;
        #pragma unroll
        for (int m = 0; m < 2; ++m) {
            const int gg0 = gtile * 128 + gbase + m * 16 + row;
            #pragma unroll
            for (int nt = 0; nt < 8; ++nt) {
                const int slice = wb * 8 + nt;
                __half* o = base + ((size_t)slice * GDIM) * 8 + kq;
                *(unsigned*)(o + (size_t)gg0 * 8)       = D[m][nt][0];
                *(unsigned*)(o + (size_t)(gg0 + 8) * 8) = D[m][nt][1];
            }
        }

        __threadfence();
        __syncthreads();
        if (tid == 0) atomicAdd(&g_flagc[dir][t >> 2], 1);
        return;
    }

    // ================= SCAN ROLE =================
    {
        __half* Wsm = (__half*)dynsm;   // [512][136]
        __shared__ __align__(16) __half h_pp[2][HDIM][8];

        const int dir   = bid >> 4;
        const int slice = bid & 15;
        const float* Whh = dir ? Whh_b : Whh_f;

        #pragma unroll 4
        for (int it = 0; it < 64; ++it) {
            const int idx = it * 256 + tid;
            const int rw = idx >> 5, q = idx & 31;
            const float4 v = __ldg((const float4*)(Whh + (size_t)rw * HDIM) + q);
            const __half2 a = __floats2half2_rn(v.x, v.y);
            const __half2 b = __floats2half2_rn(v.z, v.w);
            *(uint2*)&Wsm[rw * SC_WSTRIDE + q * 4] =
                make_uint2(*(const unsigned*)&a, *(const unsigned*)&b);
        }
        for (int i = tid; i < 2 * HDIM * 8; i += 256) ((__half*)h_pp)[i] = __float2half(0.f);
        __syncthreads();

        const int li = lane & 7, grp = lane >> 3;
        unsigned A[4][8][4];
        #pragma unroll
        for (int q = 0; q < 4; ++q) {
            const unsigned base = sptr(Wsm) +
                (((q * 128 + w * 16 + (grp & 1) * 8 + li) * SC_WSTRIDE + (grp >> 1) * 8) << 1);
            #pragma unroll
            for (int kt = 0; kt < 8; ++kt)
                ldsm4(A[q][kt][0], A[q][kt][1], A[q][kt][2], A[q][kt][3], base + kt * 32);
        }

        const int ur = w * 16 + (lane >> 2);
        const int cb = (lane & 3) * 2;
        const __half* xpd = g_xp + (size_t)dir * TLEN * 16 * GDIM * 8;
        size_t off[4];
        #pragma unroll
        for (int q = 0; q < 4; ++q)
            off[q] = ((size_t)slice * GDIM + q * 128 + ur) * 8 + cb;

        while (ld_acq(&g_flagc[dir][0]) < 16) __nanosleep(200);

        unsigned px0[4], px1[4];
        #pragma unroll
        for (int q = 0; q < 4; ++q) {
            px0[q] = *(const unsigned*)(xpd + off[q]);
            px1[q] = *(const unsigned*)(xpd + off[q] + 64);
        }

        unsigned c20 = 0u, c21 = 0u;
        unsigned hm0 = 0xFC00FC00u, hm1 = 0xFC00FC00u;

        for (int t = 0; t < TLEN; ++t) {
            // publish progress (slice-0 CTA per dir), every 16 steps
            if ((t & 15) == 0 && slice == 0 && tid == 0)
                *(volatile int*)&g_prog[dir] = t >> 2;

            // gate the next chunk every 4th step
            if ((t & 3) == 0 && (t >> 2) + 1 < TLEN / 4) {
                const int* fp = &g_flagc[dir][(t >> 2) + 1];
                while (ld_acq(fp) < 16) __nanosleep(200);
            }

            unsigned B[8][2];
            const unsigned hbase = sptr(&h_pp[t & 1][0][0]) + lane * 16;
            #pragma unroll
            for (int j = 0; j < 4; ++j)
                ldsm4t(B[2*j][0], B[2*j][1], B[2*j+1][0], B[2*j+1][1], hbase + j * 512);

            unsigned D[4][2], E[4][2];
            #pragma unroll
            for (int q = 0; q < 4; ++q) {
                D[q][0] = px0[q]; D[q][1] = px1[q];
                E[q][0] = 0u;     E[q][1] = 0u;
            }

            const __half* xn = xpd + (size_t)((t + 1 < TLEN) ? t + 1 : t) * 16 * GDIM * 8;
            #pragma unroll
            for (int q = 0; q < 4; ++q) {
                px0[q] = *(const unsigned*)(xn + off[q]);
                px1[q] = *(const unsigned*)(xn + off[q] + 64);
            }

            #pragma unroll
            for (int kt = 0; kt < 4; ++kt) {
                #pragma unroll
                for (int q = 0; q < 4; ++q) {
                    mmaf16(D[q][0], D[q][1],
                           A[q][kt][0], A[q][kt][1], A[q][kt][2], A[q][kt][3],
                           B[kt][0], B[kt][1]);
                    mmaf16(E[q][0], E[q][1],
                           A[q][kt+4][0], A[q][kt+4][1], A[q][kt+4][2], A[q][kt+4][3],
                           B[kt+4][0], B[kt+4][1]);
                }
            }
            unsigned P[4][2];
            #pragma unroll
            for (int q = 0; q < 4; ++q) {
                P[q][0] = hadd2u(D[q][0], E[q][0]);
                P[q][1] = hadd2u(D[q][1], E[q][1]);
            }

            const unsigned I0 = hsig2(P[0][0]),  I1 = hsig2(P[0][1]);
            const unsigned F0 = hsig2(P[1][0]),  F1 = hsig2(P[1][1]);
            const unsigned G0 = htanh2(P[2][0]), G1 = htanh2(P[2][1]);
            const unsigned O0 = hsig2(P[3][0]),  O1 = hsig2(P[3][1]);

            c20 = hfma2(F0, c20, hmul2(I0, G0));
            c21 = hfma2(F1, c21, hmul2(I1, G1));
            const unsigned H0 = hmul2(O0, htanh2(c20));
            const unsigned H1 = hmul2(O1, htanh2(c21));
            hm0 = hmax2u(hm0, H0);
            hm1 = hmax2u(hm1, H1);

            __half* hw = &h_pp[(t + 1) & 1][0][0];
            *(unsigned*)&hw[ur * 8 + cb]       = H0;
            *(unsigned*)&hw[(ur + 8) * 8 + cb] = H1;
            __syncthreads();
        }

        const float2 m0 = h22f2(hm0), m1 = h22f2(hm1);
        const int bb = slice * 8;
        g_pool[((size_t)dir * BATCH + bb + cb)     * HDIM + ur]     = m0.x;
        g_pool[((size_t)dir * BATCH + bb + cb + 1) * HDIM + ur]     = m0.y;
        g_pool[((size_t)dir * BATCH + bb + cb)     * HDIM + ur + 8] = m1.x;
        g_pool[((size_t)dir * BATCH + bb + cb + 1) * HDIM + ur + 8] = m1.y;
    }
}

// =====================================================================
// Kernel 3: MLP head. grid=128 (batch), 256 threads: 4 threads per h1
// unit (64 units), width-4 shuffle reduce, warp-shuffle final reduce.
// =====================================================================
__global__ void __launch_bounds__(256) mlp_kernel(
    const float* __restrict__ W1, const float* __restrict__ b1,
    const float* __restrict__ W2, const float* __restrict__ b2,
    float* __restrict__ out)
{
    __shared__ __align__(16) float pv[256];
    __shared__ float red[64];
    const int b = blockIdx.x;
    const int tid = threadIdx.x;
    const int u = tid >> 2, p = tid & 3;

    {
        const int dir = tid >> 7, uu = tid & 127;
        pv[tid] = g_pool[((size_t)dir * BATCH + b) * HDIM + uu];
    }
    __syncthreads();

    float acc = 0.f;
    const float4* w4 = (const float4*)(W1 + (size_t)u * 256 + p * 64);
    const float4* p4 = (const float4*)(pv + p * 64);
    #pragma unroll
    for (int k = 0; k < 16; ++k) {
        const float4 wv = w4[k], pvv = p4[k];
        acc += wv.x * pvv.x + wv.y * pvv.y + wv.z * pvv.z + wv.w * pvv.w;
    }
    acc += __shfl_down_sync(0xffffffffu, acc, 2, 4);
    acc += __shfl_down_sync(0xffffffffu, acc, 1, 4);
    if (p == 0) red[u] = fmaxf(acc + b1[u], 0.f) * W2[u];
    __syncthreads();

    if (tid < 32) {
        float s = red[tid] + red[tid + 32];
        #pragma unroll
        for (int d = 16; d > 0; d >>= 1) s += __shfl_down_sync(0xffffffffu, s, d);
        if (tid == 0) out[b] = 1.f / (1.f + expf(-(s + b2[0])));
    }
}

// =====================================================================
extern "C" void kernel_launch(void* const* d_in, const int* in_sizes, int n_in,
                              void* d_out, int out_size) {
    const int*   x     = (const int*)d_in[0];
    const float* table = (const float*)d_in[1];
    const float* Whh_f = (const float*)d_in[3];
    const float* bih_f = (const float*)d_in[4];
    const float* bhh_f = (const float*)d_in[5];
    const float* Wih_f = (const float*)d_in[2];
    const float* Wih_b = (const float*)d_in[6];
    const float* Whh_b = (const float*)d_in[7];
    const float* bih_b = (const float*)d_in[8];
    const float* bhh_b = (const float*)d_in[9];
    const float* W1    = (const float*)d_in[10];
    const float* b1    = (const float*)d_in[11];
    const float* W2    = (const float*)d_in[12];
    const float* b2    = (const float*)d_in[13];
    float* out = (float*)d_out;

    cudaFuncSetAttribute(mega_kernel, cudaFuncAttributeMaxDynamicSharedMemorySize, SC_SMEM);

    conv_wih_kernel<<<(GDIM * EDIM) / (256 * 4), 256>>>(Wih_f, Wih_b);
    mega_kernel<<<32 + 4096, 256, SC_SMEM>>>(x, table, Whh_f, Whh_b,
                                             bih_f, bhh_f, bih_b, bhh_b);
    mlp_kernel<<<128, 256>>>(W1, b1, W2, b2, out);
}

// round 14
// speedup vs baseline: 1.3789x; 1.0027x over previous
#include <cuda_runtime.h>
#include <cuda_fp16.h>
#include <cstdint>
#include <cstddef>

#define TLEN  512
#define BATCH 128
#define EDIM  128
#define HDIM  128
#define GDIM  512   // 4*H
#define VOCAB 100000

// Scratch (device globals — no allocation).
// xp layout: [dir][t][slice(16)][g(512)][8b]  fp16
static __device__ __half g_xp[(size_t)2 * TLEN * 16 * GDIM * 8];
static __device__ float g_pool[2 * BATCH * HDIM];
static __device__ int   g_flagc[2][TLEN / 4];   // proj completion, 16 tiles per 4-t chunk
static __device__ int   g_prog[2];              // scan progress (chunk index), per dir

// ---------- helpers ----------
#define H_HALF2 0x38003800u   // {0.5,0.5} fp16
__device__ __forceinline__ unsigned hmul2(unsigned a, unsigned b) {
    unsigned d; asm("mul.rn.f16x2 %0,%1,%2;" : "=r"(d) : "r"(a), "r"(b)); return d;
}
__device__ __forceinline__ unsigned hadd2u(unsigned a, unsigned b) {
    unsigned d; asm("add.rn.f16x2 %0,%1,%2;" : "=r"(d) : "r"(a), "r"(b)); return d;
}
__device__ __forceinline__ unsigned hfma2(unsigned a, unsigned b, unsigned c) {
    unsigned d; asm("fma.rn.f16x2 %0,%1,%2,%3;" : "=r"(d) : "r"(a), "r"(b), "r"(c)); return d;
}
__device__ __forceinline__ unsigned htanh2(unsigned a) {
    unsigned d; asm("tanh.approx.f16x2 %0,%1;" : "=r"(d) : "r"(a)); return d;
}
__device__ __forceinline__ unsigned hsig2(unsigned x) {   // 0.5*tanh(0.5x)+0.5
    return hfma2(htanh2(hmul2(x, H_HALF2)), H_HALF2, H_HALF2);
}
__device__ __forceinline__ unsigned hmax2u(unsigned a, unsigned b) {
    __half2 r = __hmax2(*(__half2*)&a, *(__half2*)&b);
    return *(unsigned*)&r;
}
__device__ __forceinline__ float2 h22f2(unsigned v) {
    return __half22float2(*(__half2*)&v);
}
__device__ __forceinline__ unsigned dup_h2(float v) {
    __half2 h = __half2half2(__float2half_rn(v));
    return *(unsigned*)&h;
}
__device__ __forceinline__ unsigned sptr(const void* p) {
    return (unsigned)__cvta_generic_to_shared(p);
}
__device__ __forceinline__ int ld_acq(const int* p) {
    int v; asm volatile("ld.acquire.gpu.global.s32 %0,[%1];" : "=r"(v) : "l"(p)); return v;
}
__device__ __forceinline__ int ld_vol(const int* p) { return *(volatile const int*)p; }
__device__ __forceinline__ void mmaf16(unsigned& d0, unsigned& d1,
                                       unsigned a0, unsigned a1, unsigned a2, unsigned a3,
                                       unsigned b0, unsigned b1) {
    asm("mma.sync.aligned.m16n8k16.row.col.f16.f16.f16.f16 "
        "{%0,%1},{%2,%3,%4,%5},{%6,%7},{%0,%1};"
        : "+r"(d0), "+r"(d1)
        : "r"(a0), "r"(a1), "r"(a2), "r"(a3), "r"(b0), "r"(b1));
}
__device__ __forceinline__ void ldsm4(unsigned& r0, unsigned& r1, unsigned& r2, unsigned& r3,
                                      unsigned addr) {
    asm volatile("ldmatrix.sync.aligned.m8n8.x4.shared.b16 {%0,%1,%2,%3}, [%4];"
                 : "=r"(r0), "=r"(r1), "=r"(r2), "=r"(r3) : "r"(addr));
}
__device__ __forceinline__ void ldsm4t(unsigned& r0, unsigned& r1, unsigned& r2, unsigned& r3,
                                       unsigned addr) {
    asm volatile("ldmatrix.sync.aligned.m8n8.x4.trans.shared.b16 {%0,%1,%2,%3}, [%4];"
                 : "=r"(r0), "=r"(r1), "=r"(r2), "=r"(r3) : "r"(addr));
}

// =====================================================================
// MEGA kernel: blocks 0-31 = persistent scan CTAs (2 dir x 16 slices);
// blocks 32..4127 = proj tiles (t-major, dirs interleaved), rate-limited
// to <= 8 chunks ahead of the scan to keep clocks high / HBM quiet.
// =====================================================================
#define PJ_STRIDE 136
#define SC_WSTRIDE 136
#define SC_SMEM (512 * SC_WSTRIDE * 2)   // 139264 B dynamic (covers proj's 69632 too)

__global__ void __launch_bounds__(256, 1) mega_kernel(
    const int* __restrict__ x, const float* __restrict__ table,
    const float* __restrict__ Wih_f, const float* __restrict__ Wih_b,
    const float* __restrict__ Whh_f, const float* __restrict__ Whh_b,
    const float* __restrict__ bih_f, const float* __restrict__ bhh_f,
    const float* __restrict__ bih_b, const float* __restrict__ bhh_b)
{
    extern __shared__ char dynsm[];
    const int tid = threadIdx.x, lane = tid & 31, w = tid >> 5;
    const int bid = blockIdx.x;

    if (bid >= 32) {
        // ================= PROJ ROLE =================
        __half* Wsm = (__half*)dynsm;             // [128][136]
        __half* Esm = Wsm + 128 * PJ_STRIDE;      // [128][136]
        __shared__ float bias_s[128];
        __shared__ int   tok_s[128];

        const int pbid  = bid - 32;
        const int gtile = pbid & 3;
        const int tt    = pbid >> 2;
        const int dir   = tt & 1;                 // dirs interleaved, t ascending
        const int t     = tt >> 1;
        const float* bi = dir ? bih_b : bih_f;
        const float* bh = dir ? bhh_b : bhh_f;
        const int tsrc  = dir ? (TLEN - 1 - t) : t;

        // backpressure: stay <= 8 chunks ahead of this dir's scan
        if (tid == 0) {
            const int chunk = t >> 2;
            while (chunk > ld_vol(&g_prog[dir]) + 8) __nanosleep(1000);
        }
        __syncthreads();

        if (tid < 128) {
            const int gg = gtile * 128 + tid;
            bias_s[tid] = bi[gg] + bh[gg];
            tok_s[tid] = x[tid * TLEN + tsrc];
        }
        __syncthreads();

        // W rows: f32 -> f16 inline (L2-hot across t-tiles)
        const float* wsrc = (dir ? Wih_b : Wih_f) + (size_t)(gtile * 128) * EDIM;
        #pragma unroll
        for (int it = 0; it < 16; ++it) {
            const int idx = it * 256 + tid;
            const int rg = idx >> 5, q = idx & 31;
            const float4 v = __ldg((const float4*)(wsrc + (size_t)rg * EDIM) + q);
            const __half2 a = __floats2half2_rn(v.x, v.y);
            const __half2 b = __floats2half2_rn(v.z, v.w);
            *(uint2*)&Wsm[rg * PJ_STRIDE + q * 4] =
                make_uint2(*(const unsigned*)&a, *(const unsigned*)&b);
        }
        // E rows: gather f32 table rows by token, convert inline
        #pragma unroll
        for (int it = 0; it < 16; ++it) {
            const int idx = it * 256 + tid;
            const int rb = idx >> 5, q = idx & 31;
            const float4 v = __ldg((const float4*)(table + (size_t)tok_s[rb] * EDIM) + q);
            const __half2 a = __floats2half2_rn(v.x, v.y);
            const __half2 b = __floats2half2_rn(v.z, v.w);
            *(uint2*)&Esm[rb * PJ_STRIDE + q * 4] =
                make_uint2(*(const unsigned*)&a, *(const unsigned*)&b);
        }
        __syncthreads();

        const int li = lane & 7, grp = lane >> 3;
        const int wg = w & 3, wb = w >> 2;
        const int gbase = wg * 32;
        const int row = lane >> 2, kq = (lane & 3) * 2;

        unsigned D[2][8][2];
        #pragma unroll
        for (int m = 0; m < 2; ++m) {
            const unsigned hb0 = dup_h2(bias_s[gbase + m * 16 + row]);
            const unsigned hb1 = dup_h2(bias_s[gbase + m * 16 + row + 8]);
            #pragma unroll
            for (int nt = 0; nt < 8; ++nt) { D[m][nt][0] = hb0; D[m][nt][1] = hb1; }
        }

        #pragma unroll
        for (int p = 0; p < 4; ++p) {
            unsigned A[2][2][4];
            #pragma unroll
            for (int m = 0; m < 2; ++m) {
                const unsigned abase = sptr(Wsm) +
                    (((gbase + m * 16 + (grp & 1) * 8 + li) * PJ_STRIDE + (grp >> 1) * 8) << 1);
                ldsm4(A[m][0][0], A[m][0][1], A[m][0][2], A[m][0][3], abase + (2 * p) * 32);
                ldsm4(A[m][1][0], A[m][1][1], A[m][1][2], A[m][1][3], abase + (2 * p + 1) * 32);
            }
            #pragma unroll
            for (int nt = 0; nt < 8; ++nt) {
                unsigned b0a, b1a, b0b, b1b;
                const unsigned eb = sptr(Esm) +
                    (((wb * 64 + nt * 8 + li) * PJ_STRIDE + grp * 8) << 1) + p * 64;
                ldsm4(b0a, b1a, b0b, b1b, eb);
                #pragma unroll
                for (int m = 0; m < 2; ++m) {
                    mmaf16(D[m][nt][0], D[m][nt][1],
                           A[m][0][0], A[m][0][1], A[m][0][2], A[m][0][3], b0a, b1a);
                    mmaf16(D[m][nt][0], D[m][nt][1],
                           A[m][1][0], A[m][1][1], A[m][1][2], A[m][1][3], b0b, b1b);
                }
            }
        }

        __half* base = g_xp + (size_t)(dir * TLEN + t) * 16 * GDIM * 8;
        #pragma unroll
        for (int m = 0; m < 2; ++m) {
            const int gg0 = gtile * 128 + gbase + m * 16 + row;
            #pragma unroll
            for (int nt = 0; nt < 8; ++nt) {
                const int slice = wb * 8 + nt;
                __half* o = base + ((size_t)slice * GDIM) * 8 + kq;
                *(unsigned*)(o + (size_t)gg0 * 8)       = D[m][nt][0];
                *(unsigned*)(o + (size_t)(gg0 + 8) * 8) = D[m][nt][1];
            }
        }

        __threadfence();
        __syncthreads();
        if (tid == 0) atomicAdd(&g_flagc[dir][t >> 2], 1);
        return;
    }

    // ================= SCAN ROLE =================
    {
        __half* Wsm = (__half*)dynsm;   // [512][136]
        __shared__ __align__(16) __half h_pp[2][HDIM][8];

        const int dir   = bid >> 4;
        const int slice = bid & 15;
        const float* Whh = dir ? Whh_b : Whh_f;

        #pragma unroll 4
        for (int it = 0; it < 64; ++it) {
            const int idx = it * 256 + tid;
            const int rw = idx >> 5, q = idx & 31;
            const float4 v = __ldg((const float4*)(Whh + (size_t)rw * HDIM) + q);
            const __half2 a = __floats2half2_rn(v.x, v.y);
            const __half2 b = __floats2half2_rn(v.z, v.w);
            *(uint2*)&Wsm[rw * SC_WSTRIDE + q * 4] =
                make_uint2(*(const unsigned*)&a, *(const unsigned*)&b);
        }
        for (int i = tid; i < 2 * HDIM * 8; i += 256) ((__half*)h_pp)[i] = __float2half(0.f);
        __syncthreads();

        const int li = lane & 7, grp = lane >> 3;
        unsigned A[4][8][4];
        #pragma unroll
        for (int q = 0; q < 4; ++q) {
            const unsigned base = sptr(Wsm) +
                (((q * 128 + w * 16 + (grp & 1) * 8 + li) * SC_WSTRIDE + (grp >> 1) * 8) << 1);
            #pragma unroll
            for (int kt = 0; kt < 8; ++kt)
                ldsm4(A[q][kt][0], A[q][kt][1], A[q][kt][2], A[q][kt][3], base + kt * 32);
        }

        const int ur = w * 16 + (lane >> 2);
        const int cb = (lane & 3) * 2;
        const __half* xpd = g_xp + (size_t)dir * TLEN * 16 * GDIM * 8;
        size_t off[4];
        #pragma unroll
        for (int q = 0; q < 4; ++q)
            off[q] = ((size_t)slice * GDIM + q * 128 + ur) * 8 + cb;

        while (ld_acq(&g_flagc[dir][0]) < 16) __nanosleep(200);

        unsigned px0[4], px1[4];
        #pragma unroll
        for (int q = 0; q < 4; ++q) {
            px0[q] = *(const unsigned*)(xpd + off[q]);
            px1[q] = *(const unsigned*)(xpd + off[q] + 64);
        }

        unsigned c20 = 0u, c21 = 0u;
        unsigned hm0 = 0xFC00FC00u, hm1 = 0xFC00FC00u;

        // gate GEMM: two interleaved 4-deep chains + combine
        #define GATE_MMA(q, p0, p1) do {                                          \
            unsigned d0 = px0c[q], d1 = px1c[q], e0 = 0u, e1 = 0u;                \
            _Pragma("unroll")                                                     \
            for (int kt = 0; kt < 4; ++kt) {                                      \
                mmaf16(d0, d1, A[q][kt][0], A[q][kt][1], A[q][kt][2], A[q][kt][3],\
                       B[kt][0], B[kt][1]);                                       \
                mmaf16(e0, e1, A[q][kt+4][0], A[q][kt+4][1], A[q][kt+4][2],       \
                       A[q][kt+4][3], B[kt+4][0], B[kt+4][1]);                    \
            }                                                                     \
            p0 = hadd2u(d0, e0); p1 = hadd2u(d1, e1);                             \
        } while (0)

        for (int t = 0; t < TLEN; ++t) {
            if ((t & 15) == 0 && slice == 0 && tid == 0)
                *(volatile int*)&g_prog[dir] = t >> 2;

            if ((t & 3) == 0 && (t >> 2) + 1 < TLEN / 4) {
                const int* fp = &g_flagc[dir][(t >> 2) + 1];
                while (ld_acq(fp) < 16) __nanosleep(200);
            }

            unsigned B[8][2];
            const unsigned hbase = sptr(&h_pp[t & 1][0][0]) + lane * 16;
            #pragma unroll
            for (int j = 0; j < 4; ++j)
                ldsm4t(B[2*j][0], B[2*j][1], B[2*j+1][0], B[2*j+1][1], hbase + j * 512);

            unsigned px0c[4], px1c[4];
            #pragma unroll
            for (int q = 0; q < 4; ++q) { px0c[q] = px0[q]; px1c[q] = px1[q]; }

            const __half* xn = xpd + (size_t)((t + 1 < TLEN) ? t + 1 : t) * 16 * GDIM * 8;
            #pragma unroll
            for (int q = 0; q < 4; ++q) {
                px0[q] = *(const unsigned*)(xn + off[q]);
                px1[q] = *(const unsigned*)(xn + off[q] + 64);
            }

            // gate-sequential: each gate's activation hides under next gate's mma
            unsigned p0, p1;
            GATE_MMA(2, p0, p1);                       // g first
            const unsigned G0 = htanh2(p0), G1 = htanh2(p1);
            GATE_MMA(0, p0, p1);                       // i
            const unsigned I0 = hsig2(p0), I1 = hsig2(p1);
            GATE_MMA(1, p0, p1);                       // f
            const unsigned F0 = hsig2(p0), F1 = hsig2(p1);
            c20 = hfma2(F0, c20, hmul2(I0, G0));       // c + tanh(c) hide under o's mma
            c21 = hfma2(F1, c21, hmul2(I1, G1));
            const unsigned T0 = htanh2(c20), T1 = htanh2(c21);
            GATE_MMA(3, p0, p1);                       // o
            const unsigned O0 = hsig2(p0), O1 = hsig2(p1);
            const unsigned H0 = hmul2(O0, T0);
            const unsigned H1 = hmul2(O1, T1);

            __half* hw = &h_pp[(t + 1) & 1][0][0];
            *(unsigned*)&hw[ur * 8 + cb]       = H0;
            *(unsigned*)&hw[(ur + 8) * 8 + cb] = H1;
            hm0 = hmax2u(hm0, H0);                     // off the barrier path
            hm1 = hmax2u(hm1, H1);
            __syncthreads();
        }
        #undef GATE_MMA

        const float2 m0 = h22f2(hm0), m1 = h22f2(hm1);
        const int bb = slice * 8;
        g_pool[((size_t)dir * BATCH + bb + cb)     * HDIM + ur]     = m0.x;
        g_pool[((size_t)dir * BATCH + bb + cb + 1) * HDIM + ur]     = m0.y;
        g_pool[((size_t)dir * BATCH + bb + cb)     * HDIM + ur + 8] = m1.x;
        g_pool[((size_t)dir * BATCH + bb + cb + 1) * HDIM + ur + 8] = m1.y;
    }
}

// =====================================================================
// Kernel 2: MLP head + flag reset for next launch (graph-replay safe:
// globals start zeroed; every launch ends with flags reset).
// =====================================================================
__global__ void __launch_bounds__(256) mlp_kernel(
    const float* __restrict__ W1, const float* __restrict__ b1,
    const float* __restrict__ W2, const float* __restrict__ b2,
    float* __restrict__ out)
{
    __shared__ __align__(16) float pv[256];
    __shared__ float red[64];
    const int b = blockIdx.x;
    const int tid = threadIdx.x;
    const int u = tid >> 2, p = tid & 3;

    if (b == 0) {                       // reset sync state for next replay
        ((int*)g_flagc)[tid] = 0;       // 2*128 ints
        if (tid < 2) g_prog[tid] = 0;
    }

    {
        const int dir = tid >> 7, uu = tid & 127;
        pv[tid] = g_pool[((size_t)dir * BATCH + b) * HDIM + uu];
    }
    __syncthreads();

    float acc = 0.f;
    const float4* w4 = (const float4*)(W1 + (size_t)u * 256 + p * 64);
    const float4* p4 = (const float4*)(pv + p * 64);
    #pragma unroll
    for (int k = 0; k < 16; ++k) {
        const float4 wv = w4[k], pvv = p4[k];
        acc += wv.x * pvv.x + wv.y * pvv.y + wv.z * pvv.z + wv.w * pvv.w;
    }
    acc += __shfl_down_sync(0xffffffffu, acc, 2, 4);
    acc += __shfl_down_sync(0xffffffffu, acc, 1, 4);
    if (p == 0) red[u] = fmaxf(acc + b1[u], 0.f) * W2[u];
    __syncthreads();

    if (tid < 32) {
        float s = red[tid] + red[tid + 32];
        #pragma unroll
        for (int d = 16; d > 0; d >>= 1) s += __shfl_down_sync(0xffffffffu, s, d);
        if (tid == 0) out[b] = 1.f / (1.f + expf(-(s + b2[0])));
    }
}

// =====================================================================
extern "C" void kernel_launch(void* const* d_in, const int* in_sizes, int n_in,
                              void* d_out, int out_size) {
    const int*   x     = (const int*)d_in[0];
    const float* table = (const float*)d_in[1];
    const float* Wih_f = (const float*)d_in[2];
    const float* Whh_f = (const float*)d_in[3];
    const float* bih_f = (const float*)d_in[4];
    const float* bhh_f = (const float*)d_in[5];
    const float* Wih_b = (const float*)d_in[6];
    const float* Whh_b = (const float*)d_in[7];
    const float* bih_b = (const float*)d_in[8];
    const float* bhh_b = (const float*)d_in[9];
    const float* W1    = (const float*)d_in[10];
    const float* b1    = (const float*)d_in[11];
    const float* W2    = (const float*)d_in[12];
    const float* b2    = (const float*)d_in[13];
    float* out = (float*)d_out;

    cudaFuncSetAttribute(mega_kernel, cudaFuncAttributeMaxDynamicSharedMemorySize, SC_SMEM);

    mega_kernel<<<32 + 4096, 256, SC_SMEM>>>(x, table, Wih_f, Wih_b, Whh_f, Whh_b,
                                             bih_f, bhh_f, bih_b, bhh_b);
    mlp_kernel<<<128, 256>>>(W1, b1, W2, b2, out);
}